// round 11
// baseline (speedup 1.0000x reference)
#include <cuda_runtime.h>
#include <cuda_bf16.h>

// SSIM loss, round 11: 128x16 tiles; V phase split into two field-pair passes
// (halves ring registers -> 4 blocks/SM) each with a 6-deep LDG prefetch ring
// (hides DRAM latency); packed f32x2 math; last-block global reduction.

#define TW 128
#define TH 16
#define RAD 5
#define INW 138         // TW + 2*RAD
#define HBW2 140        // hb row stride in u64 units
#define HW 512
#define PLANE_ELEMS (512 * 512)
#define NBLOCKS 6144

#define W0 0.00102838f
#define W1 0.00759877f
#define W2 0.03600077f
#define W3 0.10936070f
#define W4 0.21300554f
#define W5 0.26601173f

typedef unsigned long long ull;

__device__ float g_partials[NBLOCKS];
__device__ unsigned int g_counter = 0;

__device__ __forceinline__ ull f2pack(float lo, float hi) {
    ull d;
    asm("mov.b64 %0, {%1, %2};" : "=l"(d) : "f"(lo), "f"(hi));
    return d;
}
__device__ __forceinline__ void f2unpack(float& lo, float& hi, ull v) {
    asm("mov.b64 {%0, %1}, %2;" : "=f"(lo), "=f"(hi) : "l"(v));
}
__device__ __forceinline__ ull fma2(ull a, ull b, ull c) {
    ull d;
    asm("fma.rn.f32x2 %0, %1, %2, %3;" : "=l"(d) : "l"(a), "l"(b), "l"(c));
    return d;
}
#define WIDX(k) ((k) < 6 ? (k) : 10 - (k))

// One V pass: conv one packed field pair down 26 rows for one column,
// 16 output rows, 11-deep accumulator ring, 6-deep LDG prefetch.
// FIELDS=0: {p, t}. FIELDS=1: {(p+t)^2, (p-t)^2}.
template<bool INTERIOR, int FIELDS>
__device__ __forceinline__ void ssim_vpass(
    const float* __restrict__ pp, const float* __restrict__ tt,
    int x0, int y0, int tid, ull* __restrict__ hbout,
    const ull* __restrict__ Wb)
{
    for (int c = tid; c < INW; c += 256) {
        int gx = x0 - RAD + c;
        int gybase = y0 - RAD;
        bool xok = INTERIOR || ((gx >= 0) && (gx < HW));
        const float* __restrict__ prow = pp + (size_t)gybase * HW + gx;
        const float* __restrict__ trow = tt + (size_t)gybase * HW + gx;

        ull ring[11];
#pragma unroll
        for (int s = 0; s < 11; s++) ring[s] = 0ull;

        float pb[6], tb[6];
#pragma unroll
        for (int i = 0; i < 6; i++) {
            if (INTERIOR) {
                pb[i] = __ldg(prow + i * HW);
                tb[i] = __ldg(trow + i * HW);
            } else {
                int gy = gybase + i;
                pb[i] = 0.f; tb[i] = 0.f;
                if (xok && gy >= 0 && gy < HW) {
                    pb[i] = __ldg(prow + i * HW);
                    tb[i] = __ldg(trow + i * HW);
                }
            }
        }

#pragma unroll
        for (int rr = 0; rr < 26; rr++) {
            float p = pb[rr % 6];
            float t = tb[rr % 6];
            if (rr + 6 < 26) {
                int rn = rr + 6;
                if (INTERIOR) {
                    pb[rr % 6] = __ldg(prow + rn * HW);
                    tb[rr % 6] = __ldg(trow + rn * HW);
                } else {
                    int gy = gybase + rn;
                    float pv = 0.f, tv = 0.f;
                    if (xok && gy >= 0 && gy < HW) {
                        pv = __ldg(prow + rn * HW);
                        tv = __ldg(trow + rn * HW);
                    }
                    pb[rr % 6] = pv; tb[rr % 6] = tv;
                }
            }

            ull val;
            if (FIELDS == 0) {
                val = f2pack(p, t);
            } else {
                float sv = p + t;
                float dv = p - t;
                val = f2pack(sv * sv, dv * dv);
            }
#pragma unroll
            for (int j = 0; j < 16; j++) {
                int k = rr - j;
                if (k >= 0 && k <= 10)
                    ring[j % 11] = fma2(Wb[WIDX(k)], val, ring[j % 11]);
            }
            if (rr >= 10) {
                int j = rr - 10;
                int slot = j % 11;
                hbout[j * HBW2 + c] = ring[slot];
                ring[slot] = 0ull;
            }
        }
    }
}

__global__ __launch_bounds__(256, 4) void ssim_main_kernel(
    const float* __restrict__ pred,
    const float* __restrict__ target,
    float* __restrict__ out,
    float inv_count)
{
    extern __shared__ __align__(16) ull smem_raw[];
    ull* hb01 = smem_raw;                   // [16][140] u64 = 17920 B
    ull* hb23 = smem_raw + TH * HBW2;       // [16][140] u64 = 17920 B
    __shared__ float red[8];
    __shared__ bool s_last;

    const int tid = threadIdx.x;
    const int x0 = blockIdx.x * TW;
    const int y0 = blockIdx.y * TH;
    const size_t plane_off = (size_t)blockIdx.z * PLANE_ELEMS;
    const float* __restrict__ pp = pred + plane_off;
    const float* __restrict__ tt = target + plane_off;

    ull Wb[6];
    Wb[0] = f2pack(W0, W0);  Wb[1] = f2pack(W1, W1);
    Wb[2] = f2pack(W2, W2);  Wb[3] = f2pack(W3, W3);
    Wb[4] = f2pack(W4, W4);  Wb[5] = f2pack(W5, W5);

    // ---- Phase V: two passes (field pairs), independent smem regions ----
    const bool interior =
        (x0 >= RAD) && (x0 + TW + RAD <= HW) && (y0 >= RAD) && (y0 + TH + RAD <= HW);
    if (interior) {
        ssim_vpass<true, 0>(pp, tt, x0, y0, tid, hb01, Wb);
        ssim_vpass<true, 1>(pp, tt, x0, y0, tid, hb23, Wb);
    } else {
        ssim_vpass<false, 0>(pp, tt, x0, y0, tid, hb01, Wb);
        ssim_vpass<false, 1>(pp, tt, x0, y0, tid, hb23, Wb);
    }
    __syncthreads();

    // ---- Phase H: 2 quads/thread; quad = 4 consecutive x in one row ----
    const float C1 = 0.0001f;
    const float C2 = 0.0009f;
    float local = 0.f;

#pragma unroll
    for (int it = 0; it < 2; it++) {
        int h = tid + 256 * it;           // 0..511
        int r = h >> 5;                   // row 0..15
        int cg = (h & 31) << 2;           // x base 0..124
        const ull* rb01 = hb01 + r * HBW2 + cg;
        const ull* rb23 = hb23 + r * HBW2 + cg;

        float mu1[4], mu2[4], css[4], cdd[4];
        {
            ull v[16];
#pragma unroll
            for (int q = 0; q < 8; q++) {
                ulonglong2 u = *(const ulonglong2*)(rb01 + 2 * q);
                v[2 * q] = u.x; v[2 * q + 1] = u.y;
            }
            ull acc[4] = {0ull, 0ull, 0ull, 0ull};
#pragma unroll
            for (int i = 0; i < 14; i++) {
#pragma unroll
                for (int j = 0; j < 4; j++) {
                    int k = i - j;
                    if (k >= 0 && k <= 10)
                        acc[j] = fma2(Wb[WIDX(k)], v[i], acc[j]);
                }
            }
#pragma unroll
            for (int j = 0; j < 4; j++) f2unpack(mu1[j], mu2[j], acc[j]);
        }
        {
            ull v[16];
#pragma unroll
            for (int q = 0; q < 8; q++) {
                ulonglong2 u = *(const ulonglong2*)(rb23 + 2 * q);
                v[2 * q] = u.x; v[2 * q + 1] = u.y;
            }
            ull acc[4] = {0ull, 0ull, 0ull, 0ull};
#pragma unroll
            for (int i = 0; i < 14; i++) {
#pragma unroll
                for (int j = 0; j < 4; j++) {
                    int k = i - j;
                    if (k >= 0 && k <= 10)
                        acc[j] = fma2(Wb[WIDX(k)], v[i], acc[j]);
                }
            }
#pragma unroll
            for (int j = 0; j < 4; j++) f2unpack(css[j], cdd[j], acc[j]);
        }

#pragma unroll
        for (int j = 0; j < 4; j++) {
            float m1 = mu1[j], m2 = mu2[j];
            float m1s = m1 * m1;
            float m2s = m2 * m2;
            float m12 = m1 * m2;
            float ept   = 0.25f * (css[j] - cdd[j]);
            float epptt = 0.5f  * (css[j] + cdd[j]);
            float s12  = ept - m12;
            float ssum = epptt - m1s - m2s;
            float num = (2.0f * m12 + C1) * (2.0f * s12 + C2);
            float den = (m1s + m2s + C1) * (ssum + C2);
            local += __fdividef(num, den);
        }
    }

    // ---- Block reduction -> partial; last block reduces globally ----
#pragma unroll
    for (int off = 16; off > 0; off >>= 1)
        local += __shfl_down_sync(0xffffffffu, local, off);
    if ((tid & 31) == 0) red[tid >> 5] = local;
    __syncthreads();
    if (tid == 0) {
        float v = red[0] + red[1] + red[2] + red[3]
                + red[4] + red[5] + red[6] + red[7];
        int bid = (blockIdx.z * gridDim.y + blockIdx.y) * gridDim.x + blockIdx.x;
        g_partials[bid] = v;
        __threadfence();
        unsigned int n = atomicAdd(&g_counter, 1u);
        s_last = (n == NBLOCKS - 1u);
    }
    __syncthreads();

    if (s_last) {
        __threadfence();
        __shared__ double dred[8];
        const float4* __restrict__ p4 = (const float4*)g_partials;
        double acc = 0.0;
#pragma unroll
        for (int i = 0; i < NBLOCKS / 4 / 256; i++) {   // 6 iterations
            float4 v = p4[i * 256 + tid];
            acc += (double)v.x + (double)v.y + (double)v.z + (double)v.w;
        }
#pragma unroll
        for (int off = 16; off > 0; off >>= 1)
            acc += __shfl_down_sync(0xffffffffu, acc, off);
        if ((tid & 31) == 0) dred[tid >> 5] = acc;
        __syncthreads();
        if (tid == 0) {
            double s = dred[0] + dred[1] + dred[2] + dred[3]
                     + dred[4] + dred[5] + dred[6] + dred[7];
            out[0] = 1.0f - (float)(s * (double)inv_count);
            g_counter = 0;
        }
    }
}

extern "C" void kernel_launch(void* const* d_in, const int* in_sizes, int n_in,
                              void* d_out, int out_size) {
    const float* pred = (const float*)d_in[0];
    const float* target = (const float*)d_in[1];
    float* out = (float*)d_out;

    const int total = in_sizes[0];                 // N*C*H*W
    const int nplanes = total / PLANE_ELEMS;       // 48

    const size_t smem = sizeof(ull) * 2 * TH * HBW2;   // 35840 B
    cudaFuncSetAttribute(ssim_main_kernel,
                         cudaFuncAttributeMaxDynamicSharedMemorySize, (int)smem);

    dim3 grid(HW / TW, HW / TH, nplanes);          // (4, 32, 48) = 6144 blocks
    ssim_main_kernel<<<grid, 256, smem>>>(pred, target, out, 1.0f / (float)total);
}

// round 12
// speedup vs baseline: 1.2622x; 1.2622x over previous
#include <cuda_runtime.h>
#include <cuda_bf16.h>

// SSIM loss, round 12: R10 base (128x32 tiles, packed ring-FIR V, 3 blocks/SM)
// with the H phase widened to 8 outputs/thread (halo LDS bytes 64->36 B/px) and
// a row-major lane mapping + HBW2=142 padding so the wide-stride LDS.128 reads
// stay bank-conflict-free.

#define TW 128
#define TH 32
#define RAD 5
#define INW 138         // TW + 2*RAD
#define HBW2 142        // hb row stride in u64 units (1136B; 71 mod 8 = 7 -> conflict-free)
#define GROUPS 2        // 16-row groups
#define NITEMS (INW * GROUPS)   // 276
#define HW 512
#define PLANE_ELEMS (512 * 512)
#define NBLOCKS 3072

#define W0 0.00102838f
#define W1 0.00759877f
#define W2 0.03600077f
#define W3 0.10936070f
#define W4 0.21300554f
#define W5 0.26601173f

typedef unsigned long long ull;

__device__ float g_partials[NBLOCKS];
__device__ unsigned int g_counter = 0;

__device__ __forceinline__ ull f2pack(float lo, float hi) {
    ull d;
    asm("mov.b64 %0, {%1, %2};" : "=l"(d) : "f"(lo), "f"(hi));
    return d;
}
__device__ __forceinline__ void f2unpack(float& lo, float& hi, ull v) {
    asm("mov.b64 {%0, %1}, %2;" : "=f"(lo), "=f"(hi) : "l"(v));
}
__device__ __forceinline__ ull fma2(ull a, ull b, ull c) {
    ull d;
    asm("fma.rn.f32x2 %0, %1, %2, %3;" : "=l"(d) : "l"(a), "l"(b), "l"(c));
    return d;
}
#define WIDX(k) ((k) < 6 ? (k) : 10 - (k))

// Vertical 11-tap conv: one column x 16 output rows per item, 11-deep packed
// accumulator ring, 26 row loads. hb01 <- {p, t}, hb23 <- {(p+t)^2, (p-t)^2}.
template<bool INTERIOR>
__device__ __forceinline__ void ssim_phase_v(
    const float* __restrict__ pp, const float* __restrict__ tt,
    int x0, int y0, int tid, ull* __restrict__ hb01, ull* __restrict__ hb23,
    const ull* __restrict__ Wb)
{
    for (int item = tid; item < NITEMS; item += 256) {
        int g = item / INW;
        int c = item - g * INW;
        int gx = x0 - RAD + c;
        int gybase = y0 + 16 * g - RAD;
        bool xok = INTERIOR || ((gx >= 0) && (gx < HW));
        const float* __restrict__ prow = pp + (size_t)gybase * HW + gx;
        const float* __restrict__ trow = tt + (size_t)gybase * HW + gx;

        ull a01[11], a23[11];
#pragma unroll
        for (int s = 0; s < 11; s++) { a01[s] = 0ull; a23[s] = 0ull; }

#pragma unroll
        for (int rr = 0; rr < 26; rr++) {
            float p, t;
            if (INTERIOR) {
                p = __ldg(prow + rr * HW);
                t = __ldg(trow + rr * HW);
            } else {
                int gy = gybase + rr;
                p = 0.f; t = 0.f;
                if (xok && gy >= 0 && gy < HW) {
                    p = __ldg(prow + rr * HW);
                    t = __ldg(trow + rr * HW);
                }
            }
            float sv = p + t;
            float dv = p - t;
            ull pt = f2pack(p, t);
            ull sd = f2pack(sv * sv, dv * dv);
#pragma unroll
            for (int j = 0; j < 16; j++) {
                int k = rr - j;
                if (k >= 0 && k <= 10) {
                    int slot = j % 11;
                    a01[slot] = fma2(Wb[WIDX(k)], pt, a01[slot]);
                    a23[slot] = fma2(Wb[WIDX(k)], sd, a23[slot]);
                }
            }
            if (rr >= 10) {
                int j = rr - 10;
                int slot = j % 11;
                int row = 16 * g + j;
                hb01[row * HBW2 + c] = a01[slot];  a01[slot] = 0ull;
                hb23[row * HBW2 + c] = a23[slot];  a23[slot] = 0ull;
            }
        }
    }
}

__global__ __launch_bounds__(256, 3) void ssim_main_kernel(
    const float* __restrict__ pred,
    const float* __restrict__ target,
    float* __restrict__ out,
    float inv_count)
{
    extern __shared__ __align__(16) ull smem_raw[];
    ull* hb01 = smem_raw;                   // [32][142] u64 = 36352 B
    ull* hb23 = smem_raw + TH * HBW2;       // [32][142] u64 = 36352 B
    __shared__ float red[8];
    __shared__ bool s_last;

    const int tid = threadIdx.x;
    const int x0 = blockIdx.x * TW;
    const int y0 = blockIdx.y * TH;
    const size_t plane_off = (size_t)blockIdx.z * PLANE_ELEMS;
    const float* __restrict__ pp = pred + plane_off;
    const float* __restrict__ tt = target + plane_off;

    ull Wb[6];
    Wb[0] = f2pack(W0, W0);  Wb[1] = f2pack(W1, W1);
    Wb[2] = f2pack(W2, W2);  Wb[3] = f2pack(W3, W3);
    Wb[4] = f2pack(W4, W4);  Wb[5] = f2pack(W5, W5);

    // ---- Phase V ----
    const bool interior =
        (x0 >= RAD) && (x0 + TW + RAD <= HW) && (y0 >= RAD) && (y0 + TH + RAD <= HW);
    if (interior) ssim_phase_v<true >(pp, tt, x0, y0, tid, hb01, hb23, Wb);
    else          ssim_phase_v<false>(pp, tt, x0, y0, tid, hb01, hb23, Wb);
    __syncthreads();

    // ---- Phase H: 2 items/thread; item = 8 consecutive x in one row.
    // Lane mapping: consecutive lanes take consecutive ROWS (stride 1136B,
    // 16B-chunk step 71 = 7 mod 8 -> quarter-warp conflict-free).
    const float C1 = 0.0001f;
    const float C2 = 0.0009f;
    float local = 0.f;

#pragma unroll
    for (int it = 0; it < 2; it++) {
        int r = tid & 31;                         // row 0..31
        int oct = (tid >> 5) + 8 * it;            // 0..15
        int cg = oct << 3;                        // x base (u64 index), even
        const ull* rb01 = hb01 + r * HBW2 + cg;
        const ull* rb23 = hb23 + r * HBW2 + cg;

        ull acc01[8], acc23[8];
#pragma unroll
        for (int j = 0; j < 8; j++) { acc01[j] = 0ull; acc23[j] = 0ull; }

        // Stream 18 positions as 9 LDS.128 per field-pair array.
#pragma unroll
        for (int q = 0; q < 9; q++) {
            ulonglong2 u01 = *(const ulonglong2*)(rb01 + 2 * q);
            ulonglong2 u23 = *(const ulonglong2*)(rb23 + 2 * q);
#pragma unroll
            for (int half = 0; half < 2; half++) {
                int i = 2 * q + half;
                ull v01 = half ? u01.y : u01.x;
                ull v23 = half ? u23.y : u23.x;
#pragma unroll
                for (int j = 0; j < 8; j++) {
                    int k = i - j;
                    if (k >= 0 && k <= 10) {
                        acc01[j] = fma2(Wb[WIDX(k)], v01, acc01[j]);
                        acc23[j] = fma2(Wb[WIDX(k)], v23, acc23[j]);
                    }
                }
            }
        }

#pragma unroll
        for (int j = 0; j < 8; j++) {
            float m1, m2, cs, cd;
            f2unpack(m1, m2, acc01[j]);
            f2unpack(cs, cd, acc23[j]);
            float m1s = m1 * m1;
            float m2s = m2 * m2;
            float m12 = m1 * m2;
            float ept   = 0.25f * (cs - cd);     // E[pt]
            float epptt = 0.5f  * (cs + cd);     // E[pp]+E[tt]
            float s12  = ept - m12;
            float ssum = epptt - m1s - m2s;
            float num = (2.0f * m12 + C1) * (2.0f * s12 + C2);
            float den = (m1s + m2s + C1) * (ssum + C2);
            local += __fdividef(num, den);
        }
    }

    // ---- Block reduction -> partial; last block reduces globally ----
#pragma unroll
    for (int off = 16; off > 0; off >>= 1)
        local += __shfl_down_sync(0xffffffffu, local, off);
    if ((tid & 31) == 0) red[tid >> 5] = local;
    __syncthreads();
    if (tid == 0) {
        float v = red[0] + red[1] + red[2] + red[3]
                + red[4] + red[5] + red[6] + red[7];
        int bid = (blockIdx.z * gridDim.y + blockIdx.y) * gridDim.x + blockIdx.x;
        g_partials[bid] = v;
        __threadfence();
        unsigned int n = atomicAdd(&g_counter, 1u);
        s_last = (n == NBLOCKS - 1u);
    }
    __syncthreads();

    if (s_last) {
        __threadfence();
        __shared__ double dred[8];
        const float4* __restrict__ p4 = (const float4*)g_partials;
        double acc = 0.0;
#pragma unroll
        for (int i = 0; i < NBLOCKS / 4 / 256; i++) {   // 3 iterations
            float4 v = p4[i * 256 + tid];
            acc += (double)v.x + (double)v.y + (double)v.z + (double)v.w;
        }
#pragma unroll
        for (int off = 16; off > 0; off >>= 1)
            acc += __shfl_down_sync(0xffffffffu, acc, off);
        if ((tid & 31) == 0) dred[tid >> 5] = acc;
        __syncthreads();
        if (tid == 0) {
            double s = dred[0] + dred[1] + dred[2] + dred[3]
                     + dred[4] + dred[5] + dred[6] + dred[7];
            out[0] = 1.0f - (float)(s * (double)inv_count);
            g_counter = 0;
        }
    }
}

extern "C" void kernel_launch(void* const* d_in, const int* in_sizes, int n_in,
                              void* d_out, int out_size) {
    const float* pred = (const float*)d_in[0];
    const float* target = (const float*)d_in[1];
    float* out = (float*)d_out;

    const int total = in_sizes[0];                 // N*C*H*W
    const int nplanes = total / PLANE_ELEMS;       // 48

    const size_t smem = sizeof(ull) * 2 * TH * HBW2;   // 72704 B
    cudaFuncSetAttribute(ssim_main_kernel,
                         cudaFuncAttributeMaxDynamicSharedMemorySize, (int)smem);

    dim3 grid(HW / TW, HW / TH, nplanes);          // (4, 16, 48) = 3072 blocks
    ssim_main_kernel<<<grid, 256, smem>>>(pred, target, out, 1.0f / (float)total);
}

// round 13
// speedup vs baseline: 1.2669x; 1.0038x over previous
#include <cuda_runtime.h>
#include <cuda_bf16.h>

// SSIM loss, round 13: R12 base (128x32 tiles, packed ring-FIR V, 3 blocks/SM)
// + balanced V work split (full items 1/thread, leftover columns as half-items)
// + H phase as ring FIR with 16 outputs/thread (256 items exactly, SSIM on pop).

#define TW 128
#define TH 32
#define RAD 5
#define INW 138         // TW + 2*RAD
#define HBW2 142        // hb row stride in u64 (1136B; 71 mod 8 = 7 -> conflict-free)
#define HW 512
#define PLANE_ELEMS (512 * 512)
#define NBLOCKS 3072

#define W0 0.00102838f
#define W1 0.00759877f
#define W2 0.03600077f
#define W3 0.10936070f
#define W4 0.21300554f
#define W5 0.26601173f

typedef unsigned long long ull;

__device__ float g_partials[NBLOCKS];
__device__ unsigned int g_counter = 0;

__device__ __forceinline__ ull f2pack(float lo, float hi) {
    ull d;
    asm("mov.b64 %0, {%1, %2};" : "=l"(d) : "f"(lo), "f"(hi));
    return d;
}
__device__ __forceinline__ void f2unpack(float& lo, float& hi, ull v) {
    asm("mov.b64 {%0, %1}, %2;" : "=f"(lo), "=f"(hi) : "l"(v));
}
__device__ __forceinline__ ull fma2(ull a, ull b, ull c) {
    ull d;
    asm("fma.rn.f32x2 %0, %1, %2, %3;" : "=l"(d) : "l"(a), "l"(b), "l"(c));
    return d;
}
#define WIDX(k) ((k) < 6 ? (k) : 10 - (k))

// Vertical ring-FIR over one column: NLOAD raw rows -> NLOAD-10 output rows
// written to hb rows [obase, obase+NLOAD-10).
template<bool INTERIOR, int NLOAD>
__device__ __forceinline__ void vcol(
    const float* __restrict__ prow, const float* __restrict__ trow,
    bool xok, int gybase, int c, int obase,
    ull* __restrict__ hb01, ull* __restrict__ hb23, const ull* __restrict__ Wb)
{
    constexpr int NOUT = NLOAD - 10;
    ull a01[11], a23[11];
#pragma unroll
    for (int s = 0; s < 11; s++) { a01[s] = 0ull; a23[s] = 0ull; }

#pragma unroll
    for (int rr = 0; rr < NLOAD; rr++) {
        float p, t;
        if (INTERIOR) {
            p = __ldg(prow + rr * HW);
            t = __ldg(trow + rr * HW);
        } else {
            int gy = gybase + rr;
            p = 0.f; t = 0.f;
            if (xok && gy >= 0 && gy < HW) {
                p = __ldg(prow + rr * HW);
                t = __ldg(trow + rr * HW);
            }
        }
        float sv = p + t;
        float dv = p - t;
        ull pt = f2pack(p, t);
        ull sd = f2pack(sv * sv, dv * dv);
#pragma unroll
        for (int j = 0; j < NOUT; j++) {
            int k = rr - j;
            if (k >= 0 && k <= 10) {
                int slot = j % 11;
                a01[slot] = fma2(Wb[WIDX(k)], pt, a01[slot]);
                a23[slot] = fma2(Wb[WIDX(k)], sd, a23[slot]);
            }
        }
        if (rr >= 10) {
            int j = rr - 10;
            int slot = j % 11;
            int row = obase + j;
            hb01[row * HBW2 + c] = a01[slot];  a01[slot] = 0ull;
            hb23[row * HBW2 + c] = a23[slot];  a23[slot] = 0ull;
        }
    }
}

__global__ __launch_bounds__(256, 3) void ssim_main_kernel(
    const float* __restrict__ pred,
    const float* __restrict__ target,
    float* __restrict__ out,
    float inv_count)
{
    extern __shared__ __align__(16) ull smem_raw[];
    ull* hb01 = smem_raw;                   // [32][142] u64 = 36352 B
    ull* hb23 = smem_raw + TH * HBW2;       // [32][142] u64 = 36352 B
    __shared__ float red[8];
    __shared__ bool s_last;

    const int tid = threadIdx.x;
    const int x0 = blockIdx.x * TW;
    const int y0 = blockIdx.y * TH;
    const size_t plane_off = (size_t)blockIdx.z * PLANE_ELEMS;
    const float* __restrict__ pp = pred + plane_off;
    const float* __restrict__ tt = target + plane_off;

    ull Wb[6];
    Wb[0] = f2pack(W0, W0);  Wb[1] = f2pack(W1, W1);
    Wb[2] = f2pack(W2, W2);  Wb[3] = f2pack(W3, W3);
    Wb[4] = f2pack(W4, W4);  Wb[5] = f2pack(W5, W5);

    const bool interior =
        (x0 >= RAD) && (x0 + TW + RAD <= HW) && (y0 >= RAD) && (y0 + TH + RAD <= HW);

    // ---- Phase V: 256 full items (1/thread) + 40 half-items on 40 threads ----
    {
        int g = tid / INW;               // 0 for tid<138, else 1
        int c = tid - g * INW;           // full item column
        int ob = 16 * g;
        int gyb = y0 + ob - RAD;
        int gx = x0 - RAD + c;
        bool xok = interior || ((gx >= 0) && (gx < HW));
        const float* prow = pp + (size_t)gyb * HW + gx;
        const float* trow = tt + (size_t)gyb * HW + gx;
        if (interior) vcol<true , 26>(prow, trow, xok, gyb, c, ob, hb01, hb23, Wb);
        else          vcol<false, 26>(prow, trow, xok, gyb, c, ob, hb01, hb23, Wb);

        if (tid >= 216) {
            int hh = tid - 216;              // 0..39
            int c2 = 118 + (hh >> 1);        // columns 118..137 (g=1 leftovers)
            int ob2 = 16 + 8 * (hh & 1);     // output rows 16..23 or 24..31
            int gyb2 = y0 + ob2 - RAD;
            int gx2 = x0 - RAD + c2;
            bool xok2 = interior || ((gx2 >= 0) && (gx2 < HW));
            const float* prow2 = pp + (size_t)gyb2 * HW + gx2;
            const float* trow2 = tt + (size_t)gyb2 * HW + gx2;
            if (interior) vcol<true , 18>(prow2, trow2, xok2, gyb2, c2, ob2, hb01, hb23, Wb);
            else          vcol<false, 18>(prow2, trow2, xok2, gyb2, c2, ob2, hb01, hb23, Wb);
        }
    }
    __syncthreads();

    // ---- Phase H: ring FIR, 16 outputs/thread, 256 items exactly.
    // Lane mapping: lane = row (stride 1136B -> conflict-free), xg = tid>>5.
    const float C1 = 0.0001f;
    const float C2 = 0.0009f;
    float local = 0.f;
    {
        int r = tid & 31;
        int xg = tid >> 5;                  // 0..7
        int Xb = xg << 4;                   // x base 0..112 (hb col base, even)
        const ull* rb01 = hb01 + r * HBW2 + Xb;
        const ull* rb23 = hb23 + r * HBW2 + Xb;

        ull h01[11], h23[11];
#pragma unroll
        for (int s = 0; s < 11; s++) { h01[s] = 0ull; h23[s] = 0ull; }

#pragma unroll
        for (int q = 0; q < 13; q++) {       // 26 input positions
            ulonglong2 u01 = *(const ulonglong2*)(rb01 + 2 * q);
            ulonglong2 u23 = *(const ulonglong2*)(rb23 + 2 * q);
#pragma unroll
            for (int half = 0; half < 2; half++) {
                int i = 2 * q + half;
                ull v01 = half ? u01.y : u01.x;
                ull v23 = half ? u23.y : u23.x;
#pragma unroll
                for (int j = 0; j < 16; j++) {
                    int k = i - j;
                    if (k >= 0 && k <= 10) {
                        int slot = j % 11;
                        h01[slot] = fma2(Wb[WIDX(k)], v01, h01[slot]);
                        h23[slot] = fma2(Wb[WIDX(k)], v23, h23[slot]);
                    }
                }
                if (i >= 10) {
                    int j = i - 10;
                    int slot = j % 11;
                    float m1, m2, cs, cd;
                    f2unpack(m1, m2, h01[slot]);  h01[slot] = 0ull;
                    f2unpack(cs, cd, h23[slot]);  h23[slot] = 0ull;
                    float m1s = m1 * m1;
                    float m2s = m2 * m2;
                    float m12 = m1 * m2;
                    float ept   = 0.25f * (cs - cd);     // E[pt]
                    float epptt = 0.5f  * (cs + cd);     // E[pp]+E[tt]
                    float s12  = ept - m12;
                    float ssum = epptt - m1s - m2s;
                    float num = (2.0f * m12 + C1) * (2.0f * s12 + C2);
                    float den = (m1s + m2s + C1) * (ssum + C2);
                    local += __fdividef(num, den);
                }
            }
        }
    }

    // ---- Block reduction -> partial; last block reduces globally ----
#pragma unroll
    for (int off = 16; off > 0; off >>= 1)
        local += __shfl_down_sync(0xffffffffu, local, off);
    if ((tid & 31) == 0) red[tid >> 5] = local;
    __syncthreads();
    if (tid == 0) {
        float v = red[0] + red[1] + red[2] + red[3]
                + red[4] + red[5] + red[6] + red[7];
        int bid = (blockIdx.z * gridDim.y + blockIdx.y) * gridDim.x + blockIdx.x;
        g_partials[bid] = v;
        __threadfence();
        unsigned int n = atomicAdd(&g_counter, 1u);
        s_last = (n == NBLOCKS - 1u);
    }
    __syncthreads();

    if (s_last) {
        __threadfence();
        __shared__ double dred[8];
        const float4* __restrict__ p4 = (const float4*)g_partials;
        double acc = 0.0;
#pragma unroll
        for (int i = 0; i < NBLOCKS / 4 / 256; i++) {   // 3 iterations
            float4 v = p4[i * 256 + tid];
            acc += (double)v.x + (double)v.y + (double)v.z + (double)v.w;
        }
#pragma unroll
        for (int off = 16; off > 0; off >>= 1)
            acc += __shfl_down_sync(0xffffffffu, acc, off);
        if ((tid & 31) == 0) dred[tid >> 5] = acc;
        __syncthreads();
        if (tid == 0) {
            double s = dred[0] + dred[1] + dred[2] + dred[3]
                     + dred[4] + dred[5] + dred[6] + dred[7];
            out[0] = 1.0f - (float)(s * (double)inv_count);
            g_counter = 0;
        }
    }
}

extern "C" void kernel_launch(void* const* d_in, const int* in_sizes, int n_in,
                              void* d_out, int out_size) {
    const float* pred = (const float*)d_in[0];
    const float* target = (const float*)d_in[1];
    float* out = (float*)d_out;

    const int total = in_sizes[0];                 // N*C*H*W
    const int nplanes = total / PLANE_ELEMS;       // 48

    const size_t smem = sizeof(ull) * 2 * TH * HBW2;   // 72704 B
    cudaFuncSetAttribute(ssim_main_kernel,
                         cudaFuncAttributeMaxDynamicSharedMemorySize, (int)smem);

    dim3 grid(HW / TW, HW / TH, nplanes);          // (4, 16, 48) = 3072 blocks
    ssim_main_kernel<<<grid, 256, smem>>>(pred, target, out, 1.0f / (float)total);
}

// round 14
// speedup vs baseline: 1.3487x; 1.0645x over previous
#include <cuda_runtime.h>
#include <cuda_bf16.h>

// SSIM loss, round 14: 128x16 tiles, 8-row V groups + 8-output H items so both
// phases hold only 32 accumulator registers -> 64-reg budget, 4 blocks/SM.
// Packed f32x2 math, conflict-aware row-major H LDS, last-block reduction.

#define TW 128
#define TH 16
#define RAD 5
#define INW 138         // TW + 2*RAD
#define HBW2 142        // hb row stride in u64 (1136B)
#define HW 512
#define PLANE_ELEMS (512 * 512)
#define NBLOCKS 6144

#define W0 0.00102838f
#define W1 0.00759877f
#define W2 0.03600077f
#define W3 0.10936070f
#define W4 0.21300554f
#define W5 0.26601173f

typedef unsigned long long ull;

__device__ float g_partials[NBLOCKS];
__device__ unsigned int g_counter = 0;

__device__ __forceinline__ ull f2pack(float lo, float hi) {
    ull d;
    asm("mov.b64 %0, {%1, %2};" : "=l"(d) : "f"(lo), "f"(hi));
    return d;
}
__device__ __forceinline__ void f2unpack(float& lo, float& hi, ull v) {
    asm("mov.b64 {%0, %1}, %2;" : "=f"(lo), "=f"(hi) : "l"(v));
}
__device__ __forceinline__ ull fma2(ull a, ull b, ull c) {
    ull d;
    asm("fma.rn.f32x2 %0, %1, %2, %3;" : "=l"(d) : "l"(a), "l"(b), "l"(c));
    return d;
}
#define WIDX(k) ((k) < 6 ? (k) : 10 - (k))

// Vertical FIR over one column: NOUT outputs, NOUT+10 loads, NOUT-slot rings.
template<bool INTERIOR, int NOUT>
__device__ __forceinline__ void vcol(
    const float* __restrict__ prow, const float* __restrict__ trow,
    bool xok, int gybase, int c, int obase,
    ull* __restrict__ hb01, ull* __restrict__ hb23, const ull* __restrict__ Wb)
{
    constexpr int NLOAD = NOUT + 10;
    ull a01[NOUT], a23[NOUT];
#pragma unroll
    for (int s = 0; s < NOUT; s++) { a01[s] = 0ull; a23[s] = 0ull; }

#pragma unroll
    for (int rr = 0; rr < NLOAD; rr++) {
        float p, t;
        if (INTERIOR) {
            p = __ldg(prow + rr * HW);
            t = __ldg(trow + rr * HW);
        } else {
            int gy = gybase + rr;
            p = 0.f; t = 0.f;
            if (xok && gy >= 0 && gy < HW) {
                p = __ldg(prow + rr * HW);
                t = __ldg(trow + rr * HW);
            }
        }
        float sv = p + t;
        float dv = p - t;
        ull pt = f2pack(p, t);
        ull sd = f2pack(sv * sv, dv * dv);
#pragma unroll
        for (int j = 0; j < NOUT; j++) {
            int k = rr - j;
            if (k >= 0 && k <= 10) {
                a01[j] = fma2(Wb[WIDX(k)], pt, a01[j]);
                a23[j] = fma2(Wb[WIDX(k)], sd, a23[j]);
            }
        }
        if (rr >= 10) {
            int j = rr - 10;
            int row = obase + j;
            hb01[row * HBW2 + c] = a01[j];
            hb23[row * HBW2 + c] = a23[j];
        }
    }
}

__global__ __launch_bounds__(256, 4) void ssim_main_kernel(
    const float* __restrict__ pred,
    const float* __restrict__ target,
    float* __restrict__ out,
    float inv_count)
{
    extern __shared__ __align__(16) ull smem_raw[];
    ull* hb01 = smem_raw;                   // [16][142] u64 = 18176 B
    ull* hb23 = smem_raw + TH * HBW2;       // [16][142] u64 = 18176 B
    __shared__ float red[8];
    __shared__ bool s_last;

    const int tid = threadIdx.x;
    const int x0 = blockIdx.x * TW;
    const int y0 = blockIdx.y * TH;
    const size_t plane_off = (size_t)blockIdx.z * PLANE_ELEMS;
    const float* __restrict__ pp = pred + plane_off;
    const float* __restrict__ tt = target + plane_off;

    ull Wb[6];
    Wb[0] = f2pack(W0, W0);  Wb[1] = f2pack(W1, W1);
    Wb[2] = f2pack(W2, W2);  Wb[3] = f2pack(W3, W3);
    Wb[4] = f2pack(W4, W4);  Wb[5] = f2pack(W5, W5);

    const bool interior =
        (x0 >= RAD) && (x0 + TW + RAD <= HW) && (y0 >= RAD) && (y0 + TH + RAD <= HW);

    // ---- Phase V: 276 8-output items -> 256 full (1/thread) + 40 half ----
    {
        int g = tid / INW;               // 0 or 1 (8-row group)
        int c = tid - g * INW;
        int ob = 8 * g;
        int gyb = y0 + ob - RAD;
        int gx = x0 - RAD + c;
        bool xok = interior || ((gx >= 0) && (gx < HW));
        const float* prow = pp + (size_t)gyb * HW + gx;
        const float* trow = tt + (size_t)gyb * HW + gx;
        if (interior) vcol<true , 8>(prow, trow, xok, gyb, c, ob, hb01, hb23, Wb);
        else          vcol<false, 8>(prow, trow, xok, gyb, c, ob, hb01, hb23, Wb);

        // leftover items 256..275 = group-1 columns 118..137, split into
        // 4-output halves handled by threads 216..255
        if (tid >= 216) {
            int hh = tid - 216;              // 0..39
            int c2 = 118 + (hh >> 1);
            int ob2 = 8 + 4 * (hh & 1);      // rows 8..11 or 12..15
            int gyb2 = y0 + ob2 - RAD;
            int gx2 = x0 - RAD + c2;
            bool xok2 = interior || ((gx2 >= 0) && (gx2 < HW));
            const float* prow2 = pp + (size_t)gyb2 * HW + gx2;
            const float* trow2 = tt + (size_t)gyb2 * HW + gx2;
            if (interior) vcol<true , 4>(prow2, trow2, xok2, gyb2, c2, ob2, hb01, hb23, Wb);
            else          vcol<false, 4>(prow2, trow2, xok2, gyb2, c2, ob2, hb01, hb23, Wb);
        }
    }
    __syncthreads();

    // ---- Phase H: 8 outputs/thread; 16 rows x 16 x-groups = 256 items ----
    const float C1 = 0.0001f;
    const float C2 = 0.0009f;
    float local = 0.f;
    {
        int r = tid & 15;                   // row
        int xg = tid >> 4;                  // 0..15
        int Xb = xg << 3;                   // x base (even)
        const ull* rb01 = hb01 + r * HBW2 + Xb;
        const ull* rb23 = hb23 + r * HBW2 + Xb;

        ull acc01[8], acc23[8];
#pragma unroll
        for (int j = 0; j < 8; j++) { acc01[j] = 0ull; acc23[j] = 0ull; }

#pragma unroll
        for (int q = 0; q < 9; q++) {        // 18 input positions
            ulonglong2 u01 = *(const ulonglong2*)(rb01 + 2 * q);
            ulonglong2 u23 = *(const ulonglong2*)(rb23 + 2 * q);
#pragma unroll
            for (int half = 0; half < 2; half++) {
                int i = 2 * q + half;
                ull v01 = half ? u01.y : u01.x;
                ull v23 = half ? u23.y : u23.x;
#pragma unroll
                for (int j = 0; j < 8; j++) {
                    int k = i - j;
                    if (k >= 0 && k <= 10) {
                        acc01[j] = fma2(Wb[WIDX(k)], v01, acc01[j]);
                        acc23[j] = fma2(Wb[WIDX(k)], v23, acc23[j]);
                    }
                }
            }
        }

#pragma unroll
        for (int j = 0; j < 8; j++) {
            float m1, m2, cs, cd;
            f2unpack(m1, m2, acc01[j]);
            f2unpack(cs, cd, acc23[j]);
            float m1s = m1 * m1;
            float m2s = m2 * m2;
            float m12 = m1 * m2;
            float ept   = 0.25f * (cs - cd);
            float epptt = 0.5f  * (cs + cd);
            float s12  = ept - m12;
            float ssum = epptt - m1s - m2s;
            float num = (2.0f * m12 + C1) * (2.0f * s12 + C2);
            float den = (m1s + m2s + C1) * (ssum + C2);
            local += __fdividef(num, den);
        }
    }

    // ---- Block reduction -> partial; last block reduces globally ----
#pragma unroll
    for (int off = 16; off > 0; off >>= 1)
        local += __shfl_down_sync(0xffffffffu, local, off);
    if ((tid & 31) == 0) red[tid >> 5] = local;
    __syncthreads();
    if (tid == 0) {
        float v = red[0] + red[1] + red[2] + red[3]
                + red[4] + red[5] + red[6] + red[7];
        int bid = (blockIdx.z * gridDim.y + blockIdx.y) * gridDim.x + blockIdx.x;
        g_partials[bid] = v;
        __threadfence();
        unsigned int n = atomicAdd(&g_counter, 1u);
        s_last = (n == NBLOCKS - 1u);
    }
    __syncthreads();

    if (s_last) {
        __threadfence();
        __shared__ double dred[8];
        const float4* __restrict__ p4 = (const float4*)g_partials;
        double acc = 0.0;
#pragma unroll
        for (int i = 0; i < NBLOCKS / 4 / 256; i++) {   // 6 iterations
            float4 v = p4[i * 256 + tid];
            acc += (double)v.x + (double)v.y + (double)v.z + (double)v.w;
        }
#pragma unroll
        for (int off = 16; off > 0; off >>= 1)
            acc += __shfl_down_sync(0xffffffffu, acc, off);
        if ((tid & 31) == 0) dred[tid >> 5] = acc;
        __syncthreads();
        if (tid == 0) {
            double s = dred[0] + dred[1] + dred[2] + dred[3]
                     + dred[4] + dred[5] + dred[6] + dred[7];
            out[0] = 1.0f - (float)(s * (double)inv_count);
            g_counter = 0;
        }
    }
}

extern "C" void kernel_launch(void* const* d_in, const int* in_sizes, int n_in,
                              void* d_out, int out_size) {
    const float* pred = (const float*)d_in[0];
    const float* target = (const float*)d_in[1];
    float* out = (float*)d_out;

    const int total = in_sizes[0];                 // N*C*H*W
    const int nplanes = total / PLANE_ELEMS;       // 48

    const size_t smem = sizeof(ull) * 2 * TH * HBW2;   // 36352 B
    cudaFuncSetAttribute(ssim_main_kernel,
                         cudaFuncAttributeMaxDynamicSharedMemorySize, (int)smem);

    dim3 grid(HW / TW, HW / TH, nplanes);          // (4, 32, 48) = 6144 blocks
    ssim_main_kernel<<<grid, 256, smem>>>(pred, target, out, 1.0f / (float)total);
}